// round 12
// baseline (speedup 1.0000x reference)
#include <cuda_runtime.h>
#include <math_constants.h>

typedef unsigned long long ull;

#define N_NODES 4096
#define HID 128
#define KNN 10
#define NH 4
#define DH 32
#define NE 65536
#define MQ 2048
#define SMAX 18
#define JSPLIT 2
#define KNN_SMEM (((64*130 + 32*64) * 8) + 128 * 4)

// ---------------- scratch (device globals; no allocation allowed) ----------
__device__ __align__(16) float g_x [N_NODES*HID];
__device__ __align__(16) float g_sq[N_NODES];
__device__ __align__(16) int   g_nn[N_NODES*KNN];
__device__ __align__(16) ull   g_cand[JSPLIT*N_NODES*KNN];
__device__ __align__(16) float g_q [N_NODES*HID];
__device__ __align__(16) float g_k [N_NODES*HID];
__device__ __align__(16) float g_v [N_NODES*HID];
__device__ __align__(16) float g_ao[N_NODES*HID];
__device__ __align__(16) float g_hf[N_NODES*HID];
__device__ __align__(16) float g_x2[N_NODES*HID];
__device__ __align__(16) float g_xw[N_NODES*HID];
__device__ __align__(16) float g_ef[N_NODES*HID];
__device__ __align__(16) float g_o1[N_NODES*HID];
__device__ __align__(16) float g_y [N_NODES*HID];
__device__ __align__(16) float g_x3[N_NODES*HID];
__device__ __align__(16) int   g_dcnt[N_NODES];
__device__ __align__(16) int   g_bcnt[N_NODES];
__device__ __align__(16) float g_mean[HID];
__device__ __align__(16) float g_var [HID];
__device__ __align__(16) float g_po[SMAX*NH*N_NODES*DH];
__device__ __align__(16) float g_pl[SMAX*NH*N_NODES];

// ---------------- f32x2 packed helpers (Blackwell FFMA2) -------------------
__device__ __forceinline__ ull fma2(ull a, ull b, ull c) {
    ull d;
    asm("fma.rn.f32x2 %0, %1, %2, %3;" : "=l"(d) : "l"(a), "l"(b), "l"(c));
    return d;
}
__device__ __forceinline__ ull pack2(float lo, float hi) {
    ull r;
    asm("mov.b64 %0, {%1, %2};" : "=l"(r) : "f"(lo), "f"(hi));
    return r;
}
__device__ __forceinline__ float2 unpack2(ull a) {
    float lo, hi;
    asm("mov.b64 {%0, %1}, %2;" : "=f"(lo), "=f"(hi) : "l"(a));
    return make_float2(lo, hi);
}
__device__ __forceinline__ unsigned fkey(float f) {
    unsigned u = __float_as_uint(f);
    return (u & 0x80000000u) ? ~u : (u | 0x80000000u);
}
__device__ __forceinline__ void red4(float* p, float4 v) {
    asm volatile("red.global.add.v4.f32 [%0], {%1, %2, %3, %4};"
                 :: "l"(p), "f"(v.x), "f"(v.y), "f"(v.z), "f"(v.w) : "memory");
}

// ---------------- elementwise ----------------------------------------------
__global__ void concat_k(const float* __restrict__ e1, const float* __restrict__ e2) {
    int t = blockIdx.x * 256 + threadIdx.x;            // N*HID/4 threads
    const float4* s = (t < 2048 * HID / 4) ? (const float4*)e1 : (const float4*)e2 - 2048 * HID / 4;
    ((float4*)g_x)[t] = s[t];
}

__global__ void row_sq() {                              // warp per row
    int w = threadIdx.x >> 5, lane = threadIdx.x & 31;
    int i = blockIdx.x * 8 + w;
    float s = 0.f;
#pragma unroll
    for (int u = 0; u < 4; ++u) {
        float v = g_x[i * HID + u * 32 + lane];
        s = fmaf(v, v, s);
    }
#pragma unroll
    for (int off = 16; off; off >>= 1) s += __shfl_xor_sync(0xffffffffu, s, off);
    if (lane == 0) g_sq[i] = s;
}

// ---------------- kNN v5: 4q/warp + register-prefetch pipelined tiles ------
__device__ __forceinline__ void insert10(float s, int j, float (&bd)[10], int (&bi)[10]) {
    if (s < bd[9]) {
        bd[9] = s; bi[9] = j;
#pragma unroll
        for (int t = 9; t > 0; --t) {
            if (bd[t] < bd[t - 1]) {
                float td = bd[t]; bd[t] = bd[t - 1]; bd[t - 1] = td;
                int   ti = bi[t]; bi[t] = bi[t - 1]; bi[t - 1] = ti;
            }
        }
    }
}

__device__ __forceinline__ void cand_merge(int slot, float (&bd)[10], int (&bi)[10], int lane) {
    for (int r = 0; r < KNN; ++r) {
        ull key = ((ull)fkey(bd[0]) << 32) | (unsigned)bi[0];
        ull mykey = key;
#pragma unroll
        for (int off = 16; off; off >>= 1) {
            ull o = __shfl_xor_sync(0xffffffffu, key, off);
            key = (o < key) ? o : key;
        }
        if (lane == 0) g_cand[slot * KNN + r] = key;
        if (mykey == key) {
#pragma unroll
            for (int t = 0; t < 9; ++t) { bd[t] = bd[t + 1]; bi[t] = bi[t + 1]; }
            bd[9] = 3.4e38f; bi[9] = 0x7fffffff;
        }
    }
}

extern __shared__ ull knn_smem[];
__global__ __launch_bounds__(256) void knn_kernel() {
    ull*  xt  = knn_smem;                       // [64][130] padded
    ull*  qs  = knn_smem + 64 * 130;            // [32][64]
    float* sqs = (float*)(knn_smem + 64 * 130 + 32 * 64);  // [128]
    const int w = threadIdx.x >> 5, lane = threadIdx.x & 31;
    const int tid = threadIdx.x;
    const int i0 = blockIdx.x * 32;
    const int sp = blockIdx.y;
    const ull* xu = (const ull*)g_x;   // row stride 64 pairs

    for (int u = tid; u < 32 * 64; u += 256)
        qs[u] = xu[(i0 + (u >> 6)) * 64 + (u & 63)];

    float bd[4][10]; int bi[4][10];
#pragma unroll
    for (int qi = 0; qi < 4; ++qi)
#pragma unroll
        for (int t = 0; t < 10; ++t) { bd[qi][t] = 3.4e38f; bi[qi][t] = 0x7fffffff; }

    const int j0 = sp * (N_NODES / JSPLIT);
    const int NT = (N_NODES / JSPLIT) / 128;    // 16 tiles

    ull pr[32];
    float prsq = 0.f;

    // preload tile 0 into regs, then to smem
#pragma unroll
    for (int r = 0; r < 32; ++r) {
        int u = tid + 256 * r;
        pr[r] = xu[(j0 + (u >> 6)) * 64 + (u & 63)];
    }
    if (tid < 128) prsq = g_sq[j0 + tid];
#pragma unroll
    for (int r = 0; r < 32; ++r) {
        int u = tid + 256 * r;
        xt[(u & 63) * 130 + (u >> 6)] = pr[r];
    }
    if (tid < 128) sqs[tid] = prsq;
    __syncthreads();

    for (int ti = 0; ti < NT; ++ti) {
        const int jt = j0 + ti * 128;
        // issue next tile's loads into registers (overlaps with compute below)
        if (ti + 1 < NT) {
            const int jn = jt + 128;
#pragma unroll
            for (int r = 0; r < 32; ++r) {
                int u = tid + 256 * r;
                pr[r] = xu[(jn + (u >> 6)) * 64 + (u & 63)];
            }
            if (tid < 128) prsq = g_sq[jn + tid];
        }

        // compute current tile
        ull a[4][4];
#pragma unroll
        for (int qi = 0; qi < 4; ++qi)
#pragma unroll
            for (int c = 0; c < 4; ++c) a[qi][c] = 0ull;

#pragma unroll 4
        for (int dp = 0; dp < 64; ++dp) {
            ull q0 = qs[(w * 4 + 0) * 64 + dp];
            ull q1 = qs[(w * 4 + 1) * 64 + dp];
            ull q2 = qs[(w * 4 + 2) * 64 + dp];
            ull q3 = qs[(w * 4 + 3) * 64 + dp];
            const ull* xr = &xt[dp * 130 + lane];
#pragma unroll
            for (int c = 0; c < 4; ++c) {
                ull xv = xr[c * 32];
                a[0][c] = fma2(q0, xv, a[0][c]);
                a[1][c] = fma2(q1, xv, a[1][c]);
                a[2][c] = fma2(q2, xv, a[2][c]);
                a[3][c] = fma2(q3, xv, a[3][c]);
            }
        }
#pragma unroll
        for (int c = 0; c < 4; ++c) {
            int j = jt + lane + c * 32;
            float sq = sqs[lane + c * 32];
#pragma unroll
            for (int qi = 0; qi < 4; ++qi) {
                float2 t = unpack2(a[qi][c]);
                insert10(fmaf(-2.f, t.x + t.y, sq), j, bd[qi], bi[qi]);
            }
        }

        // swap: store prefetched tile into smem
        if (ti + 1 < NT) {
            __syncthreads();
#pragma unroll
            for (int r = 0; r < 32; ++r) {
                int u = tid + 256 * r;
                xt[(u & 63) * 130 + (u >> 6)] = pr[r];
            }
            if (tid < 128) sqs[tid] = prsq;
            __syncthreads();
        }
    }

#pragma unroll
    for (int qi = 0; qi < 4; ++qi)
        cand_merge(sp * N_NODES + i0 + w * 4 + qi, bd[qi], bi[qi], lane);
}

__global__ void knn_final() {                     // warp per query, merge JSPLIT lists
    int q = blockIdx.x * 8 + (threadIdx.x >> 5);
    int lane = threadIdx.x & 31;
    ull key = (lane < JSPLIT * KNN)
        ? g_cand[((lane / KNN) * N_NODES + q) * KNN + (lane % KNN)]
        : ~0ull;
    for (int r = 0; r < KNN; ++r) {
        ull t = key;
#pragma unroll
        for (int off = 16; off; off >>= 1) {
            ull o = __shfl_xor_sync(0xffffffffu, t, off);
            t = (o < t) ? o : t;
        }
        if (key == t) key = ~0ull;                // keys unique across splits
        if (lane == 0) g_nn[q * KNN + r] = (int)(unsigned)(t & 0xffffffffu);
    }
}

// ---------------- batched GEMM: C_z[M,128] = a_z*(A_z B_z^T + bias_z) -------
__global__ __launch_bounds__(256) void gemm_nt(const float* __restrict__ A0,
                                               const float* __restrict__ A12,
                                               const float* __restrict__ B,
                                               const float* __restrict__ bias,
                                               float* __restrict__ C0,
                                               float* __restrict__ C1,
                                               float* __restrict__ C2,
                                               int M0, float alpha0) {
    const int z = blockIdx.z;
    const int m0 = blockIdx.y * 64, n0 = blockIdx.x * 64;
    if (z == 0 && m0 >= M0) return;
    const float* A = (z == 0) ? A0 : A12;
    float* C = (z == 0) ? C0 : ((z == 1) ? C1 : C2);
    const float* Bz = B + z * 128 * 128;
    const float* bp = bias ? bias + z * 128 : (const float*)0;
    const float alpha = (z == 0) ? alpha0 : 1.f;

    __shared__ float As[64][33], Bs[64][33];
    const int tx = threadIdx.x & 15, ty = threadIdx.x >> 4;
    float acc[4][4] = {};
    const int lrow = threadIdx.x >> 2, lc0 = (threadIdx.x & 3) * 8;
    for (int kc = 0; kc < 128; kc += 32) {
        __syncthreads();
        float4 a0 = *(const float4*)&A[(m0 + lrow) * 128 + kc + lc0];
        float4 a1 = *(const float4*)&A[(m0 + lrow) * 128 + kc + lc0 + 4];
        float4 b0 = *(const float4*)&Bz[(n0 + lrow) * 128 + kc + lc0];
        float4 b1 = *(const float4*)&Bz[(n0 + lrow) * 128 + kc + lc0 + 4];
        As[lrow][lc0 + 0] = a0.x; As[lrow][lc0 + 1] = a0.y; As[lrow][lc0 + 2] = a0.z; As[lrow][lc0 + 3] = a0.w;
        As[lrow][lc0 + 4] = a1.x; As[lrow][lc0 + 5] = a1.y; As[lrow][lc0 + 6] = a1.z; As[lrow][lc0 + 7] = a1.w;
        Bs[lrow][lc0 + 0] = b0.x; Bs[lrow][lc0 + 1] = b0.y; Bs[lrow][lc0 + 2] = b0.z; Bs[lrow][lc0 + 3] = b0.w;
        Bs[lrow][lc0 + 4] = b1.x; Bs[lrow][lc0 + 5] = b1.y; Bs[lrow][lc0 + 6] = b1.z; Bs[lrow][lc0 + 7] = b1.w;
        __syncthreads();
#pragma unroll
        for (int k = 0; k < 32; ++k) {
            float a[4], b[4];
#pragma unroll
            for (int ii = 0; ii < 4; ++ii) a[ii] = As[ty * 4 + ii][k];
#pragma unroll
            for (int jj = 0; jj < 4; ++jj) b[jj] = Bs[tx * 4 + jj][k];
#pragma unroll
            for (int ii = 0; ii < 4; ++ii)
#pragma unroll
                for (int jj = 0; jj < 4; ++jj) acc[ii][jj] = fmaf(a[ii], b[jj], acc[ii][jj]);
        }
    }
#pragma unroll
    for (int ii = 0; ii < 4; ++ii)
#pragma unroll
        for (int jj = 0; jj < 4; ++jj) {
            int cc = n0 + tx * 4 + jj;
            float bv = bp ? bp[cc] : 0.f;
            C[(m0 + ty * 4 + ii) * HID + cc] = alpha * (acc[ii][jj] + bv);
        }
}

// ---------------- flash attention v5: NO online max (scores bounded) -------
__global__ __launch_bounds__(128) void flash_partial(const float* __restrict__ Q,
                                                     const float* __restrict__ Kx,
                                                     const float* __restrict__ Vx,
                                                     int Lq, int Lk, int nsplit) {
    __shared__ ull Ks[32][16], Vs[32][16];
    const int h = blockIdx.y, s = blockIdx.z;
    const int tid = threadIdx.x;
    const int q0 = blockIdx.x * 256 + tid;         // q1 = q0 + 128
    const ull* Qu = (const ull*)Q;
    const ulonglong2* Ku2 = (const ulonglong2*)Kx;
    const ulonglong2* Vu2 = (const ulonglong2*)Vx;

    ull qr0[16], qr1[16];
#pragma unroll
    for (int dp = 0; dp < 16; ++dp) {
        qr0[dp] = Qu[q0 * 64 + h * 16 + dp];
        qr1[dp] = Qu[(q0 + 128) * 64 + h * 16 + dp];
    }

    float l0 = 0.f, l1 = 0.f;
    ull o0[16], o1[16];
#pragma unroll
    for (int dp = 0; dp < 16; ++dp) { o0[dp] = 0ull; o1[dp] = 0ull; }

    const int ntile = Lk >> 5;
    const int t0 = (ntile * s) / nsplit;
    const int t1 = (ntile * (s + 1)) / nsplit;

    for (int t = t0; t < t1; ++t) {
        __syncthreads();
        const int kt = t << 5;
#pragma unroll
        for (int r = 0; r < 2; ++r) {
            int u = tid + r * 128;
            int j = u >> 3, dpp = u & 7;
            ((ulonglong2*)Ks[j])[dpp] = Ku2[(kt + j) * 32 + h * 8 + dpp];
            ((ulonglong2*)Vs[j])[dpp] = Vu2[(kt + j) * 32 + h * 8 + dpp];
        }
        __syncthreads();

#pragma unroll 4
        for (int j = 0; j < 32; ++j) {
            const ulonglong2* kr = (const ulonglong2*)Ks[j];
            ull a0e = 0ull, a0o = 0ull, a1e = 0ull, a1o = 0ull;
#pragma unroll
            for (int i = 0; i < 8; ++i) {
                ulonglong2 kv = kr[i];
                a0e = fma2(qr0[2 * i],     kv.x, a0e);
                a0o = fma2(qr0[2 * i + 1], kv.y, a0o);
                a1e = fma2(qr1[2 * i],     kv.x, a1e);
                a1o = fma2(qr1[2 * i + 1], kv.y, a1o);
            }
            float2 u0 = unpack2(a0e), v0 = unpack2(a0o);
            float2 u1 = unpack2(a1e), v1 = unpack2(a1o);
            float p0 = __expf((u0.x + u0.y) + (v0.x + v0.y));
            float p1 = __expf((u1.x + u1.y) + (v1.x + v1.y));
            l0 += p0; l1 += p1;
            ull p02 = pack2(p0, p0), p12 = pack2(p1, p1);
            const ulonglong2* vr = (const ulonglong2*)Vs[j];
#pragma unroll
            for (int i = 0; i < 8; ++i) {
                ulonglong2 vv = vr[i];
                o0[2 * i]     = fma2(p02, vv.x, o0[2 * i]);
                o0[2 * i + 1] = fma2(p02, vv.y, o0[2 * i + 1]);
                o1[2 * i]     = fma2(p12, vv.x, o1[2 * i]);
                o1[2 * i + 1] = fma2(p12, vv.y, o1[2 * i + 1]);
            }
        }
    }

    ull* po = (ull*)g_po;
    const int pid0 = (s * NH + h) * Lq + q0;
    const int pid1 = pid0 + 128;
    g_pl[pid0] = l0;
    g_pl[pid1] = l1;
#pragma unroll
    for (int dp = 0; dp < 16; ++dp) {
        po[pid0 * 16 + dp] = o0[dp];
        po[pid1 * 16 + dp] = o1[dp];
    }
}

__global__ void flash_combine(float* __restrict__ ao, int Lq, int nsplit) {  // warp per (q,h)
    int gw = blockIdx.x * 8 + (threadIdx.x >> 5);
    int lane = threadIdx.x & 31;
    int q = gw >> 2, h = gw & 3;
    float l = 0.f, ov = 0.f;
    for (int s = 0; s < nsplit; ++s) {
        int pid = (s * NH + h) * Lq + q;
        l  += g_pl[pid];
        ov += g_po[pid * 32 + lane];
    }
    ao[q * HID + h * 32 + lane] = ov / l;
}

// ---------------- neighbor gather-sum (float4) -------------------------------
__global__ void gather_sum() {
    int t = blockIdx.x * 256 + threadIdx.x;   // N*32 threads
    int i = t >> 5, d4 = (t & 31) * 4;
    float4 acc = *(const float4*)&g_x[i * HID + d4];
#pragma unroll
    for (int k = 0; k < KNN; ++k) {
        float4 v = *(const float4*)&g_hf[g_nn[i * KNN + k] * HID + d4];
        acc.x += v.x; acc.y += v.y; acc.z += v.z; acc.w += v.w;
    }
    *(float4*)&g_x2[i * HID + d4] = acc;
}

// ---------------- hypergraph conv -------------------------------------------
__global__ void zero_buffers() {
    int t = blockIdx.x * 256 + threadIdx.x;
    g_ef[t] = 0.f; g_o1[t] = 0.f;
    if (t < N_NODES) { g_dcnt[t] = 0; g_bcnt[t] = 0; }
}

__global__ void he_count(const int* __restrict__ ei) {
    int e = blockIdx.x * 256 + threadIdx.x;
    if (e < NE) {
        atomicAdd(&g_dcnt[ei[e]], 1);
        atomicAdd(&g_bcnt[ei[NE + e]], 1);
    }
}

__global__ void scatter1(const int* __restrict__ ei) {   // node -> hyperedge (v4 red)
    int t = blockIdx.x * 256 + threadIdx.x;   // NE*32 threads
    int e = t >> 5, d4 = (t & 31) * 4;
    int nd = ei[e], hh = ei[NE + e];
    float4 v = *(const float4*)&g_xw[nd * HID + d4];
    red4(&g_ef[hh * HID + d4], v);
}

__global__ void scatter2(const int* __restrict__ ei) {   // hyperedge -> node (B^-1 fused)
    int t = blockIdx.x * 256 + threadIdx.x;   // NE*32 threads
    int e = t >> 5, d4 = (t & 31) * 4;
    int nd = ei[e], hh = ei[NE + e];
    float binv = 1.f / (float)g_bcnt[hh];
    float4 v = *(const float4*)&g_ef[hh * HID + d4];
    v.x *= binv; v.y *= binv; v.z *= binv; v.w *= binv;
    red4(&g_o1[nd * HID + d4], v);
}

__global__ void conv_finalize(const float* __restrict__ convb) {
    int t = blockIdx.x * 256 + threadIdx.x;
    int i = t >> 7, d = t & 127;
    int dc = g_dcnt[i];
    float dinv = dc > 0 ? 1.f / (float)dc : 0.f;
    g_y[t] = g_o1[t] * dinv + convb[d];
}

// ---------------- batchnorm + elu -------------------------------------------
__global__ void bn_stats() {                              // block per column
    __shared__ float ss[256], ss2[256];
    int c = blockIdx.x;
    float s = 0.f, s2 = 0.f;
    for (int i = threadIdx.x; i < N_NODES; i += 256) {
        float v = g_y[i * HID + c];
        s += v; s2 = fmaf(v, v, s2);
    }
    ss[threadIdx.x] = s; ss2[threadIdx.x] = s2;
    __syncthreads();
    for (int st = 128; st > 0; st >>= 1) {
        if (threadIdx.x < st) { ss[threadIdx.x] += ss[threadIdx.x + st]; ss2[threadIdx.x] += ss2[threadIdx.x + st]; }
        __syncthreads();
    }
    if (threadIdx.x == 0) {
        float mean = ss[0] / (float)N_NODES;
        g_mean[c] = mean;
        g_var[c] = ss2[0] / (float)N_NODES - mean * mean;
    }
}

__global__ void bn_apply_elu(const float* __restrict__ gamma, const float* __restrict__ beta) {
    int t = blockIdx.x * 256 + threadIdx.x;
    int d = t & 127;
    float v = (g_y[t] - g_mean[d]) * rsqrtf(g_var[d] + 1e-5f) * gamma[d] + beta[d];
    g_x3[t] = v > 0.f ? v : expm1f(v);
}

// ---------------- host orchestration ----------------------------------------
static float* dsym(const void* sym) {
    void* p = 0;
    cudaGetSymbolAddress(&p, sym);
    return (float*)p;
}

extern "C" void kernel_launch(void* const* d_in, const int* in_sizes, int n_in,
                              void* d_out, int out_size) {
    const float* embs1   = (const float*)d_in[0];
    const float* embs2   = (const float*)d_in[1];
    const float* m_embs  = (const float*)d_in[2];
    const int*   eidx    = (const int*)  d_in[3];
    const float* he_init = (const float*)d_in[4];
    const float* a_in_w  = (const float*)d_in[5];
    const float* a_in_b  = (const float*)d_in[6];
    const float* a_out_w = (const float*)d_in[7];
    const float* a_out_b = (const float*)d_in[8];
    const float* conv_w  = (const float*)d_in[9];
    const float* conv_b  = (const float*)d_in[10];
    const float* bn_g    = (const float*)d_in[11];
    const float* bn_b    = (const float*)d_in[12];
    const float* m_in_w  = (const float*)d_in[13];
    const float* m_in_b  = (const float*)d_in[14];
    const float* m_out_w = (const float*)d_in[15];
    const float* m_out_b = (const float*)d_in[16];
    float* out = (float*)d_out;

    float* p_x  = dsym(g_x);
    float* p_q  = dsym(g_q);
    float* p_k  = dsym(g_k);
    float* p_v  = dsym(g_v);
    float* p_ao = dsym(g_ao);
    float* p_hf = dsym(g_hf);
    float* p_x2 = dsym(g_x2);
    float* p_xw = dsym(g_xw);
    float* p_x3 = dsym(g_x3);

    cudaFuncSetAttribute(knn_kernel, cudaFuncAttributeMaxDynamicSharedMemorySize, KNN_SMEM);

    const float rs = 0.17677669529663687f;  // 1/sqrt(DH)
    const int EW = N_NODES * HID / 256;

    // 1-3: concat, row_sq, MHA1 QKV projection
    concat_k<<<N_NODES * HID / 1024, 256>>>(embs1, embs2);
    row_sq<<<N_NODES / 8, 256>>>();
    gemm_nt<<<dim3(2, 64, 3), 256>>>(he_init, p_x, a_in_w, a_in_b,
                                     p_q, p_k, p_v, N_NODES, rs);

    // 4: MHA1 flash attention (nsplit=9 -> 576 blocks = 1.95 waves)  <-- ncu slot
    flash_partial<<<dim3(N_NODES / 256, NH, 9), 128>>>(p_q, p_k, p_v, N_NODES, N_NODES, 9);

    // 5-6: kNN v5 + candidate merge
    knn_kernel<<<dim3(N_NODES / 32, JSPLIT), 256, KNN_SMEM>>>();
    knn_final<<<N_NODES / 8, 256>>>();

    // 7-8: conv prep (independent)
    zero_buffers<<<EW, 256>>>();
    he_count<<<NE / 256, 256>>>(eidx);

    // 9-10: combine + out-proj
    flash_combine<<<N_NODES * NH / 8, 256>>>(p_ao, N_NODES, 9);
    gemm_nt<<<dim3(2, 64, 1), 256>>>(p_ao, p_ao, a_out_w, a_out_b,
                                     p_hf, p_hf, p_hf, N_NODES, 1.f);

    // 11: x2 = x + sum_k hf[nn]
    gather_sum<<<N_NODES * 32 / 256, 256>>>();

    // 12-15: hypergraph conv
    gemm_nt<<<dim3(2, 64, 1), 256>>>(p_x2, p_x2, conv_w, (const float*)0,
                                     p_xw, p_xw, p_xw, N_NODES, 1.f);
    scatter1<<<NE * 32 / 256, 256>>>(eidx);
    scatter2<<<NE * 32 / 256, 256>>>(eidx);
    conv_finalize<<<EW, 256>>>(conv_b);

    // 16-17: batchnorm + elu
    bn_stats<<<HID, 256>>>();
    bn_apply_elu<<<EW, 256>>>(bn_g, bn_b);

    // 18-21: MHA2 (nsplit=18 -> 576 blocks = 1.95 waves)
    gemm_nt<<<dim3(2, 64, 3), 256>>>(m_embs, p_x3, m_in_w, m_in_b,
                                     p_q, p_k, p_v, MQ, rs);
    flash_partial<<<dim3(MQ / 256, NH, 18), 128>>>(p_q, p_k, p_v, MQ, N_NODES, 18);
    flash_combine<<<MQ * NH / 8, 256>>>(p_ao, MQ, 18);
    gemm_nt<<<dim3(2, 32, 1), 256>>>(p_ao, p_ao, m_out_w, m_out_b,
                                     out, out, out, MQ, 1.f);

    (void)in_sizes; (void)n_in; (void)out_size;
}

// round 13
// speedup vs baseline: 1.0225x; 1.0225x over previous
#include <cuda_runtime.h>
#include <math_constants.h>

typedef unsigned long long ull;

#define N_NODES 4096
#define HID 128
#define KNN 10
#define NH 4
#define DH 32
#define NE 65536
#define MQ 2048
#define SMAX 14
#define JSPLIT 2
#define KNN_SMEM (((64*130 + 32*64) * 8) + 128 * 4)

// ---------------- scratch (device globals; no allocation allowed) ----------
__device__ __align__(16) float g_x [N_NODES*HID];
__device__ __align__(16) float g_sq[N_NODES];
__device__ __align__(16) int   g_nn[N_NODES*KNN];
__device__ __align__(16) ull   g_cand[JSPLIT*N_NODES*KNN];
__device__ __align__(16) float g_q [N_NODES*HID];
__device__ __align__(16) float g_k [N_NODES*HID];
__device__ __align__(16) float g_v [N_NODES*HID];
__device__ __align__(16) float g_ao[N_NODES*HID];
__device__ __align__(16) float g_hf[N_NODES*HID];
__device__ __align__(16) float g_x2[N_NODES*HID];
__device__ __align__(16) float g_xw[N_NODES*HID];
__device__ __align__(16) float g_ef[N_NODES*HID];
__device__ __align__(16) float g_o1[N_NODES*HID];
__device__ __align__(16) float g_y [N_NODES*HID];
__device__ __align__(16) float g_x3[N_NODES*HID];
__device__ __align__(16) int   g_dcnt[N_NODES];
__device__ __align__(16) int   g_bcnt[N_NODES];
__device__ __align__(16) float g_mean[HID];
__device__ __align__(16) float g_var [HID];
__device__ __align__(16) float g_po[SMAX*NH*N_NODES*DH];
__device__ __align__(16) float g_pl[SMAX*NH*N_NODES];

// ---------------- f32x2 packed helpers (Blackwell FFMA2) -------------------
__device__ __forceinline__ ull fma2(ull a, ull b, ull c) {
    ull d;
    asm("fma.rn.f32x2 %0, %1, %2, %3;" : "=l"(d) : "l"(a), "l"(b), "l"(c));
    return d;
}
__device__ __forceinline__ ull pack2(float lo, float hi) {
    ull r;
    asm("mov.b64 %0, {%1, %2};" : "=l"(r) : "f"(lo), "f"(hi));
    return r;
}
__device__ __forceinline__ float2 unpack2(ull a) {
    float lo, hi;
    asm("mov.b64 {%0, %1}, %2;" : "=f"(lo), "=f"(hi) : "l"(a));
    return make_float2(lo, hi);
}
__device__ __forceinline__ unsigned fkey(float f) {
    unsigned u = __float_as_uint(f);
    return (u & 0x80000000u) ? ~u : (u | 0x80000000u);
}
__device__ __forceinline__ void red4(float* p, float4 v) {
    asm volatile("red.global.add.v4.f32 [%0], {%1, %2, %3, %4};"
                 :: "l"(p), "f"(v.x), "f"(v.y), "f"(v.z), "f"(v.w) : "memory");
}

// ---------------- elementwise ----------------------------------------------
__global__ void concat_k(const float* __restrict__ e1, const float* __restrict__ e2) {
    int t = blockIdx.x * 256 + threadIdx.x;            // N*HID/4 threads
    const float4* s = (t < 2048 * HID / 4) ? (const float4*)e1 : (const float4*)e2 - 2048 * HID / 4;
    ((float4*)g_x)[t] = s[t];
}

__global__ void row_sq() {                              // warp per row
    int w = threadIdx.x >> 5, lane = threadIdx.x & 31;
    int i = blockIdx.x * 8 + w;
    float s = 0.f;
#pragma unroll
    for (int u = 0; u < 4; ++u) {
        float v = g_x[i * HID + u * 32 + lane];
        s = fmaf(v, v, s);
    }
#pragma unroll
    for (int off = 16; off; off >>= 1) s += __shfl_xor_sync(0xffffffffu, s, off);
    if (lane == 0) g_sq[i] = s;
}

// ---------------- kNN v5: 4q/warp + register-prefetch pipelined tiles ------
__device__ __forceinline__ void insert10(float s, int j, float (&bd)[10], int (&bi)[10]) {
    if (s < bd[9]) {
        bd[9] = s; bi[9] = j;
#pragma unroll
        for (int t = 9; t > 0; --t) {
            if (bd[t] < bd[t - 1]) {
                float td = bd[t]; bd[t] = bd[t - 1]; bd[t - 1] = td;
                int   ti = bi[t]; bi[t] = bi[t - 1]; bi[t - 1] = ti;
            }
        }
    }
}

__device__ __forceinline__ void cand_merge(int slot, float (&bd)[10], int (&bi)[10], int lane) {
    for (int r = 0; r < KNN; ++r) {
        ull key = ((ull)fkey(bd[0]) << 32) | (unsigned)bi[0];
        ull mykey = key;
#pragma unroll
        for (int off = 16; off; off >>= 1) {
            ull o = __shfl_xor_sync(0xffffffffu, key, off);
            key = (o < key) ? o : key;
        }
        if (lane == 0) g_cand[slot * KNN + r] = key;
        if (mykey == key) {
#pragma unroll
            for (int t = 0; t < 9; ++t) { bd[t] = bd[t + 1]; bi[t] = bi[t + 1]; }
            bd[9] = 3.4e38f; bi[9] = 0x7fffffff;
        }
    }
}

extern __shared__ ull knn_smem[];
__global__ __launch_bounds__(256) void knn_kernel() {
    ull*  xt  = knn_smem;                       // [64][130] padded
    ull*  qs  = knn_smem + 64 * 130;            // [32][64]
    float* sqs = (float*)(knn_smem + 64 * 130 + 32 * 64);  // [128]
    const int w = threadIdx.x >> 5, lane = threadIdx.x & 31;
    const int tid = threadIdx.x;
    const int i0 = blockIdx.x * 32;
    const int sp = blockIdx.y;
    const ull* xu = (const ull*)g_x;   // row stride 64 pairs

    for (int u = tid; u < 32 * 64; u += 256)
        qs[u] = xu[(i0 + (u >> 6)) * 64 + (u & 63)];

    float bd[4][10]; int bi[4][10];
#pragma unroll
    for (int qi = 0; qi < 4; ++qi)
#pragma unroll
        for (int t = 0; t < 10; ++t) { bd[qi][t] = 3.4e38f; bi[qi][t] = 0x7fffffff; }

    const int j0 = sp * (N_NODES / JSPLIT);
    const int NT = (N_NODES / JSPLIT) / 128;    // 16 tiles

    ull pr[32];
    float prsq = 0.f;

    // preload tile 0 into regs, then to smem
#pragma unroll
    for (int r = 0; r < 32; ++r) {
        int u = tid + 256 * r;
        pr[r] = xu[(j0 + (u >> 6)) * 64 + (u & 63)];
    }
    if (tid < 128) prsq = g_sq[j0 + tid];
#pragma unroll
    for (int r = 0; r < 32; ++r) {
        int u = tid + 256 * r;
        xt[(u & 63) * 130 + (u >> 6)] = pr[r];
    }
    if (tid < 128) sqs[tid] = prsq;
    __syncthreads();

    for (int ti = 0; ti < NT; ++ti) {
        const int jt = j0 + ti * 128;
        // issue next tile's loads into registers (overlaps with compute below)
        if (ti + 1 < NT) {
            const int jn = jt + 128;
#pragma unroll
            for (int r = 0; r < 32; ++r) {
                int u = tid + 256 * r;
                pr[r] = xu[(jn + (u >> 6)) * 64 + (u & 63)];
            }
            if (tid < 128) prsq = g_sq[jn + tid];
        }

        // compute current tile
        ull a[4][4];
#pragma unroll
        for (int qi = 0; qi < 4; ++qi)
#pragma unroll
            for (int c = 0; c < 4; ++c) a[qi][c] = 0ull;

#pragma unroll 4
        for (int dp = 0; dp < 64; ++dp) {
            ull q0 = qs[(w * 4 + 0) * 64 + dp];
            ull q1 = qs[(w * 4 + 1) * 64 + dp];
            ull q2 = qs[(w * 4 + 2) * 64 + dp];
            ull q3 = qs[(w * 4 + 3) * 64 + dp];
            const ull* xr = &xt[dp * 130 + lane];
#pragma unroll
            for (int c = 0; c < 4; ++c) {
                ull xv = xr[c * 32];
                a[0][c] = fma2(q0, xv, a[0][c]);
                a[1][c] = fma2(q1, xv, a[1][c]);
                a[2][c] = fma2(q2, xv, a[2][c]);
                a[3][c] = fma2(q3, xv, a[3][c]);
            }
        }
#pragma unroll
        for (int c = 0; c < 4; ++c) {
            int j = jt + lane + c * 32;
            float sq = sqs[lane + c * 32];
#pragma unroll
            for (int qi = 0; qi < 4; ++qi) {
                float2 t = unpack2(a[qi][c]);
                insert10(fmaf(-2.f, t.x + t.y, sq), j, bd[qi], bi[qi]);
            }
        }

        // swap: store prefetched tile into smem
        if (ti + 1 < NT) {
            __syncthreads();
#pragma unroll
            for (int r = 0; r < 32; ++r) {
                int u = tid + 256 * r;
                xt[(u & 63) * 130 + (u >> 6)] = pr[r];
            }
            if (tid < 128) sqs[tid] = prsq;
            __syncthreads();
        }
    }

#pragma unroll
    for (int qi = 0; qi < 4; ++qi)
        cand_merge(sp * N_NODES + i0 + w * 4 + qi, bd[qi], bi[qi], lane);
}

__global__ void knn_final() {                     // warp per query, merge JSPLIT lists
    int q = blockIdx.x * 8 + (threadIdx.x >> 5);
    int lane = threadIdx.x & 31;
    ull key = (lane < JSPLIT * KNN)
        ? g_cand[((lane / KNN) * N_NODES + q) * KNN + (lane % KNN)]
        : ~0ull;
    for (int r = 0; r < KNN; ++r) {
        ull t = key;
#pragma unroll
        for (int off = 16; off; off >>= 1) {
            ull o = __shfl_xor_sync(0xffffffffu, t, off);
            t = (o < t) ? o : t;
        }
        if (key == t) key = ~0ull;                // keys unique across splits
        if (lane == 0) g_nn[q * KNN + r] = (int)(unsigned)(t & 0xffffffffu);
    }
}

// ---------------- batched GEMM: C_z[M,128] = a_z*(A_z B_z^T + bias_z) -------
__global__ __launch_bounds__(256) void gemm_nt(const float* __restrict__ A0,
                                               const float* __restrict__ A12,
                                               const float* __restrict__ B,
                                               const float* __restrict__ bias,
                                               float* __restrict__ C0,
                                               float* __restrict__ C1,
                                               float* __restrict__ C2,
                                               int M0, float alpha0) {
    const int z = blockIdx.z;
    const int m0 = blockIdx.y * 64, n0 = blockIdx.x * 64;
    if (z == 0 && m0 >= M0) return;
    const float* A = (z == 0) ? A0 : A12;
    float* C = (z == 0) ? C0 : ((z == 1) ? C1 : C2);
    const float* Bz = B + z * 128 * 128;
    const float* bp = bias ? bias + z * 128 : (const float*)0;
    const float alpha = (z == 0) ? alpha0 : 1.f;

    __shared__ float As[64][33], Bs[64][33];
    const int tx = threadIdx.x & 15, ty = threadIdx.x >> 4;
    float acc[4][4] = {};
    const int lrow = threadIdx.x >> 2, lc0 = (threadIdx.x & 3) * 8;
    for (int kc = 0; kc < 128; kc += 32) {
        __syncthreads();
        float4 a0 = *(const float4*)&A[(m0 + lrow) * 128 + kc + lc0];
        float4 a1 = *(const float4*)&A[(m0 + lrow) * 128 + kc + lc0 + 4];
        float4 b0 = *(const float4*)&Bz[(n0 + lrow) * 128 + kc + lc0];
        float4 b1 = *(const float4*)&Bz[(n0 + lrow) * 128 + kc + lc0 + 4];
        As[lrow][lc0 + 0] = a0.x; As[lrow][lc0 + 1] = a0.y; As[lrow][lc0 + 2] = a0.z; As[lrow][lc0 + 3] = a0.w;
        As[lrow][lc0 + 4] = a1.x; As[lrow][lc0 + 5] = a1.y; As[lrow][lc0 + 6] = a1.z; As[lrow][lc0 + 7] = a1.w;
        Bs[lrow][lc0 + 0] = b0.x; Bs[lrow][lc0 + 1] = b0.y; Bs[lrow][lc0 + 2] = b0.z; Bs[lrow][lc0 + 3] = b0.w;
        Bs[lrow][lc0 + 4] = b1.x; Bs[lrow][lc0 + 5] = b1.y; Bs[lrow][lc0 + 6] = b1.z; Bs[lrow][lc0 + 7] = b1.w;
        __syncthreads();
#pragma unroll
        for (int k = 0; k < 32; ++k) {
            float a[4], b[4];
#pragma unroll
            for (int ii = 0; ii < 4; ++ii) a[ii] = As[ty * 4 + ii][k];
#pragma unroll
            for (int jj = 0; jj < 4; ++jj) b[jj] = Bs[tx * 4 + jj][k];
#pragma unroll
            for (int ii = 0; ii < 4; ++ii)
#pragma unroll
                for (int jj = 0; jj < 4; ++jj) acc[ii][jj] = fmaf(a[ii], b[jj], acc[ii][jj]);
        }
    }
#pragma unroll
    for (int ii = 0; ii < 4; ++ii)
#pragma unroll
        for (int jj = 0; jj < 4; ++jj) {
            int cc = n0 + tx * 4 + jj;
            float bv = bp ? bp[cc] : 0.f;
            C[(m0 + ty * 4 + ii) * HID + cc] = alpha * (acc[ii][jj] + bv);
        }
}

// ---------------- flash attention v5: NO online max (scores bounded) -------
// __launch_bounds__(128, 3): cap regs (~166) for 3 blocks/SM = 12 warps,
// lifting the 8-warp latency ceiling seen at 174 regs / 2 blocks.
__global__ __launch_bounds__(128, 3) void flash_partial(const float* __restrict__ Q,
                                                        const float* __restrict__ Kx,
                                                        const float* __restrict__ Vx,
                                                        int Lq, int Lk, int nsplit) {
    __shared__ ull Ks[32][16], Vs[32][16];
    const int h = blockIdx.y, s = blockIdx.z;
    const int tid = threadIdx.x;
    const int q0 = blockIdx.x * 256 + tid;         // q1 = q0 + 128
    const ull* Qu = (const ull*)Q;
    const ulonglong2* Ku2 = (const ulonglong2*)Kx;
    const ulonglong2* Vu2 = (const ulonglong2*)Vx;

    ull qr0[16], qr1[16];
#pragma unroll
    for (int dp = 0; dp < 16; ++dp) {
        qr0[dp] = Qu[q0 * 64 + h * 16 + dp];
        qr1[dp] = Qu[(q0 + 128) * 64 + h * 16 + dp];
    }

    float l0 = 0.f, l1 = 0.f;
    ull o0[16], o1[16];
#pragma unroll
    for (int dp = 0; dp < 16; ++dp) { o0[dp] = 0ull; o1[dp] = 0ull; }

    const int ntile = Lk >> 5;
    const int t0 = (ntile * s) / nsplit;
    const int t1 = (ntile * (s + 1)) / nsplit;

    for (int t = t0; t < t1; ++t) {
        __syncthreads();
        const int kt = t << 5;
#pragma unroll
        for (int r = 0; r < 2; ++r) {
            int u = tid + r * 128;
            int j = u >> 3, dpp = u & 7;
            ((ulonglong2*)Ks[j])[dpp] = Ku2[(kt + j) * 32 + h * 8 + dpp];
            ((ulonglong2*)Vs[j])[dpp] = Vu2[(kt + j) * 32 + h * 8 + dpp];
        }
        __syncthreads();

#pragma unroll 4
        for (int j = 0; j < 32; ++j) {
            const ulonglong2* kr = (const ulonglong2*)Ks[j];
            ull a0e = 0ull, a0o = 0ull, a1e = 0ull, a1o = 0ull;
#pragma unroll
            for (int i = 0; i < 8; ++i) {
                ulonglong2 kv = kr[i];
                a0e = fma2(qr0[2 * i],     kv.x, a0e);
                a0o = fma2(qr0[2 * i + 1], kv.y, a0o);
                a1e = fma2(qr1[2 * i],     kv.x, a1e);
                a1o = fma2(qr1[2 * i + 1], kv.y, a1o);
            }
            float2 u0 = unpack2(a0e), v0 = unpack2(a0o);
            float2 u1 = unpack2(a1e), v1 = unpack2(a1o);
            float p0 = __expf((u0.x + u0.y) + (v0.x + v0.y));
            float p1 = __expf((u1.x + u1.y) + (v1.x + v1.y));
            l0 += p0; l1 += p1;
            ull p02 = pack2(p0, p0), p12 = pack2(p1, p1);
            const ulonglong2* vr = (const ulonglong2*)Vs[j];
#pragma unroll
            for (int i = 0; i < 8; ++i) {
                ulonglong2 vv = vr[i];
                o0[2 * i]     = fma2(p02, vv.x, o0[2 * i]);
                o0[2 * i + 1] = fma2(p02, vv.y, o0[2 * i + 1]);
                o1[2 * i]     = fma2(p12, vv.x, o1[2 * i]);
                o1[2 * i + 1] = fma2(p12, vv.y, o1[2 * i + 1]);
            }
        }
    }

    ull* po = (ull*)g_po;
    const int pid0 = (s * NH + h) * Lq + q0;
    const int pid1 = pid0 + 128;
    g_pl[pid0] = l0;
    g_pl[pid1] = l1;
#pragma unroll
    for (int dp = 0; dp < 16; ++dp) {
        po[pid0 * 16 + dp] = o0[dp];
        po[pid1 * 16 + dp] = o1[dp];
    }
}

__global__ void flash_combine(float* __restrict__ ao, int Lq, int nsplit) {  // warp per (q,h)
    int gw = blockIdx.x * 8 + (threadIdx.x >> 5);
    int lane = threadIdx.x & 31;
    int q = gw >> 2, h = gw & 3;
    float l = 0.f, ov = 0.f;
    for (int s = 0; s < nsplit; ++s) {
        int pid = (s * NH + h) * Lq + q;
        l  += g_pl[pid];
        ov += g_po[pid * 32 + lane];
    }
    ao[q * HID + h * 32 + lane] = ov / l;
}

// ---------------- neighbor gather-sum (float4) -------------------------------
__global__ void gather_sum() {
    int t = blockIdx.x * 256 + threadIdx.x;   // N*32 threads
    int i = t >> 5, d4 = (t & 31) * 4;
    float4 acc = *(const float4*)&g_x[i * HID + d4];
#pragma unroll
    for (int k = 0; k < KNN; ++k) {
        float4 v = *(const float4*)&g_hf[g_nn[i * KNN + k] * HID + d4];
        acc.x += v.x; acc.y += v.y; acc.z += v.z; acc.w += v.w;
    }
    *(float4*)&g_x2[i * HID + d4] = acc;
}

// ---------------- hypergraph conv -------------------------------------------
__global__ void zero_buffers() {
    int t = blockIdx.x * 256 + threadIdx.x;
    g_ef[t] = 0.f; g_o1[t] = 0.f;
    if (t < N_NODES) { g_dcnt[t] = 0; g_bcnt[t] = 0; }
}

__global__ void he_count(const int* __restrict__ ei) {
    int e = blockIdx.x * 256 + threadIdx.x;
    if (e < NE) {
        atomicAdd(&g_dcnt[ei[e]], 1);
        atomicAdd(&g_bcnt[ei[NE + e]], 1);
    }
}

__global__ void scatter1(const int* __restrict__ ei) {   // node -> hyperedge (v4 red)
    int t = blockIdx.x * 256 + threadIdx.x;   // NE*32 threads
    int e = t >> 5, d4 = (t & 31) * 4;
    int nd = ei[e], hh = ei[NE + e];
    float4 v = *(const float4*)&g_xw[nd * HID + d4];
    red4(&g_ef[hh * HID + d4], v);
}

__global__ void scatter2(const int* __restrict__ ei) {   // hyperedge -> node (B^-1 fused)
    int t = blockIdx.x * 256 + threadIdx.x;   // NE*32 threads
    int e = t >> 5, d4 = (t & 31) * 4;
    int nd = ei[e], hh = ei[NE + e];
    float binv = 1.f / (float)g_bcnt[hh];
    float4 v = *(const float4*)&g_ef[hh * HID + d4];
    v.x *= binv; v.y *= binv; v.z *= binv; v.w *= binv;
    red4(&g_o1[nd * HID + d4], v);
}

__global__ void conv_finalize(const float* __restrict__ convb) {
    int t = blockIdx.x * 256 + threadIdx.x;
    int i = t >> 7, d = t & 127;
    int dc = g_dcnt[i];
    float dinv = dc > 0 ? 1.f / (float)dc : 0.f;
    g_y[t] = g_o1[t] * dinv + convb[d];
}

// ---------------- batchnorm + elu -------------------------------------------
__global__ void bn_stats() {                              // block per column
    __shared__ float ss[256], ss2[256];
    int c = blockIdx.x;
    float s = 0.f, s2 = 0.f;
    for (int i = threadIdx.x; i < N_NODES; i += 256) {
        float v = g_y[i * HID + c];
        s += v; s2 = fmaf(v, v, s2);
    }
    ss[threadIdx.x] = s; ss2[threadIdx.x] = s2;
    __syncthreads();
    for (int st = 128; st > 0; st >>= 1) {
        if (threadIdx.x < st) { ss[threadIdx.x] += ss[threadIdx.x + st]; ss2[threadIdx.x] += ss2[threadIdx.x + st]; }
        __syncthreads();
    }
    if (threadIdx.x == 0) {
        float mean = ss[0] / (float)N_NODES;
        g_mean[c] = mean;
        g_var[c] = ss2[0] / (float)N_NODES - mean * mean;
    }
}

__global__ void bn_apply_elu(const float* __restrict__ gamma, const float* __restrict__ beta) {
    int t = blockIdx.x * 256 + threadIdx.x;
    int d = t & 127;
    float v = (g_y[t] - g_mean[d]) * rsqrtf(g_var[d] + 1e-5f) * gamma[d] + beta[d];
    g_x3[t] = v > 0.f ? v : expm1f(v);
}

// ---------------- host orchestration ----------------------------------------
static float* dsym(const void* sym) {
    void* p = 0;
    cudaGetSymbolAddress(&p, sym);
    return (float*)p;
}

extern "C" void kernel_launch(void* const* d_in, const int* in_sizes, int n_in,
                              void* d_out, int out_size) {
    const float* embs1   = (const float*)d_in[0];
    const float* embs2   = (const float*)d_in[1];
    const float* m_embs  = (const float*)d_in[2];
    const int*   eidx    = (const int*)  d_in[3];
    const float* he_init = (const float*)d_in[4];
    const float* a_in_w  = (const float*)d_in[5];
    const float* a_in_b  = (const float*)d_in[6];
    const float* a_out_w = (const float*)d_in[7];
    const float* a_out_b = (const float*)d_in[8];
    const float* conv_w  = (const float*)d_in[9];
    const float* conv_b  = (const float*)d_in[10];
    const float* bn_g    = (const float*)d_in[11];
    const float* bn_b    = (const float*)d_in[12];
    const float* m_in_w  = (const float*)d_in[13];
    const float* m_in_b  = (const float*)d_in[14];
    const float* m_out_w = (const float*)d_in[15];
    const float* m_out_b = (const float*)d_in[16];
    float* out = (float*)d_out;

    float* p_x  = dsym(g_x);
    float* p_q  = dsym(g_q);
    float* p_k  = dsym(g_k);
    float* p_v  = dsym(g_v);
    float* p_ao = dsym(g_ao);
    float* p_hf = dsym(g_hf);
    float* p_x2 = dsym(g_x2);
    float* p_xw = dsym(g_xw);
    float* p_x3 = dsym(g_x3);

    cudaFuncSetAttribute(knn_kernel, cudaFuncAttributeMaxDynamicSharedMemorySize, KNN_SMEM);

    const float rs = 0.17677669529663687f;  // 1/sqrt(DH)
    const int EW = N_NODES * HID / 256;

    // 1-3: concat, row_sq, MHA1 QKV projection
    concat_k<<<N_NODES * HID / 1024, 256>>>(embs1, embs2);
    row_sq<<<N_NODES / 8, 256>>>();
    gemm_nt<<<dim3(2, 64, 3), 256>>>(he_init, p_x, a_in_w, a_in_b,
                                     p_q, p_k, p_v, N_NODES, rs);

    // 4: MHA1 flash attention (nsplit=7 -> 448 blocks)  <-- ncu slot
    flash_partial<<<dim3(N_NODES / 256, NH, 7), 128>>>(p_q, p_k, p_v, N_NODES, N_NODES, 7);

    // 5-6: kNN v5 + candidate merge
    knn_kernel<<<dim3(N_NODES / 32, JSPLIT), 256, KNN_SMEM>>>();
    knn_final<<<N_NODES / 8, 256>>>();

    // 7-8: conv prep (independent)
    zero_buffers<<<EW, 256>>>();
    he_count<<<NE / 256, 256>>>(eidx);

    // 9-10: combine + out-proj
    flash_combine<<<N_NODES * NH / 8, 256>>>(p_ao, N_NODES, 7);
    gemm_nt<<<dim3(2, 64, 1), 256>>>(p_ao, p_ao, a_out_w, a_out_b,
                                     p_hf, p_hf, p_hf, N_NODES, 1.f);

    // 11: x2 = x + sum_k hf[nn]
    gather_sum<<<N_NODES * 32 / 256, 256>>>();

    // 12-15: hypergraph conv
    gemm_nt<<<dim3(2, 64, 1), 256>>>(p_x2, p_x2, conv_w, (const float*)0,
                                     p_xw, p_xw, p_xw, N_NODES, 1.f);
    scatter1<<<NE * 32 / 256, 256>>>(eidx);
    scatter2<<<NE * 32 / 256, 256>>>(eidx);
    conv_finalize<<<EW, 256>>>(conv_b);

    // 16-17: batchnorm + elu
    bn_stats<<<HID, 256>>>();
    bn_apply_elu<<<EW, 256>>>(bn_g, bn_b);

    // 18-21: MHA2 (nsplit=14 -> 448 blocks)
    gemm_nt<<<dim3(2, 64, 3), 256>>>(m_embs, p_x3, m_in_w, m_in_b,
                                     p_q, p_k, p_v, MQ, rs);
    flash_partial<<<dim3(MQ / 256, NH, 14), 128>>>(p_q, p_k, p_v, MQ, N_NODES, 14);
    flash_combine<<<MQ * NH / 8, 256>>>(p_ao, MQ, 14);
    gemm_nt<<<dim3(2, 32, 1), 256>>>(p_ao, p_ao, m_out_w, m_out_b,
                                     out, out, out, MQ, 1.f);

    (void)in_sizes; (void)n_in; (void)out_size;
}

// round 14
// speedup vs baseline: 1.0530x; 1.0299x over previous
#include <cuda_runtime.h>
#include <math_constants.h>

typedef unsigned long long ull;

#define N_NODES 4096
#define HID 128
#define KNN 10
#define NH 4
#define DH 32
#define NE 65536
#define MQ 2048
#define SMAX 14
#define JSPLIT 2
#define KNN_SMEM (((64*130 + 32*64) * 8) + 128 * 4)

// ---------------- scratch (device globals; no allocation allowed) ----------
__device__ __align__(16) float g_x [N_NODES*HID];
__device__ __align__(16) float g_sq[N_NODES];
__device__ __align__(16) int   g_nn[N_NODES*KNN];
__device__ __align__(16) ull   g_cand[JSPLIT*N_NODES*KNN];
__device__ __align__(16) float g_q [N_NODES*HID];
__device__ __align__(16) float g_k [N_NODES*HID];
__device__ __align__(16) float g_v [N_NODES*HID];
__device__ __align__(16) float g_ao[N_NODES*HID];
__device__ __align__(16) float g_hf[N_NODES*HID];
__device__ __align__(16) float g_x2[N_NODES*HID];
__device__ __align__(16) float g_xw[N_NODES*HID];
__device__ __align__(16) float g_ef[N_NODES*HID];
__device__ __align__(16) float g_o1[N_NODES*HID];
__device__ __align__(16) float g_y [N_NODES*HID];
__device__ __align__(16) float g_x3[N_NODES*HID];
__device__ __align__(16) int   g_dcnt[N_NODES];
__device__ __align__(16) int   g_bcnt[N_NODES];
__device__ __align__(16) float g_mean[HID];
__device__ __align__(16) float g_var [HID];
__device__ __align__(16) float g_po[SMAX*NH*N_NODES*DH];
__device__ __align__(16) float g_pl[SMAX*NH*N_NODES];

// ---------------- side stream for knn overlap (created pre-main; reused) ---
static cudaStream_t g_s2;
static cudaEvent_t  g_e1, g_e2;
static struct KLInit {
    KLInit() {
        cudaStreamCreateWithFlags(&g_s2, cudaStreamNonBlocking);
        cudaEventCreateWithFlags(&g_e1, cudaEventDisableTiming);
        cudaEventCreateWithFlags(&g_e2, cudaEventDisableTiming);
    }
} g_kl_init;

// ---------------- f32x2 packed helpers (Blackwell FFMA2) -------------------
__device__ __forceinline__ ull fma2(ull a, ull b, ull c) {
    ull d;
    asm("fma.rn.f32x2 %0, %1, %2, %3;" : "=l"(d) : "l"(a), "l"(b), "l"(c));
    return d;
}
__device__ __forceinline__ ull pack2(float lo, float hi) {
    ull r;
    asm("mov.b64 %0, {%1, %2};" : "=l"(r) : "f"(lo), "f"(hi));
    return r;
}
__device__ __forceinline__ float2 unpack2(ull a) {
    float lo, hi;
    asm("mov.b64 {%0, %1}, %2;" : "=f"(lo), "=f"(hi) : "l"(a));
    return make_float2(lo, hi);
}
__device__ __forceinline__ unsigned fkey(float f) {
    unsigned u = __float_as_uint(f);
    return (u & 0x80000000u) ? ~u : (u | 0x80000000u);
}
__device__ __forceinline__ void red4(float* p, float4 v) {
    asm volatile("red.global.add.v4.f32 [%0], {%1, %2, %3, %4};"
                 :: "l"(p), "f"(v.x), "f"(v.y), "f"(v.z), "f"(v.w) : "memory");
}

// ---------------- elementwise ----------------------------------------------
__global__ void concat_k(const float* __restrict__ e1, const float* __restrict__ e2) {
    int t = blockIdx.x * 256 + threadIdx.x;            // N*HID/4 threads
    const float4* s = (t < 2048 * HID / 4) ? (const float4*)e1 : (const float4*)e2 - 2048 * HID / 4;
    ((float4*)g_x)[t] = s[t];
}

__global__ void row_sq() {                              // warp per row
    int w = threadIdx.x >> 5, lane = threadIdx.x & 31;
    int i = blockIdx.x * 8 + w;
    float s = 0.f;
#pragma unroll
    for (int u = 0; u < 4; ++u) {
        float v = g_x[i * HID + u * 32 + lane];
        s = fmaf(v, v, s);
    }
#pragma unroll
    for (int off = 16; off; off >>= 1) s += __shfl_xor_sync(0xffffffffu, s, off);
    if (lane == 0) g_sq[i] = s;
}

// ---------------- kNN v5: 4q/warp + register-prefetch pipelined tiles ------
__device__ __forceinline__ void insert10(float s, int j, float (&bd)[10], int (&bi)[10]) {
    if (s < bd[9]) {
        bd[9] = s; bi[9] = j;
#pragma unroll
        for (int t = 9; t > 0; --t) {
            if (bd[t] < bd[t - 1]) {
                float td = bd[t]; bd[t] = bd[t - 1]; bd[t - 1] = td;
                int   ti = bi[t]; bi[t] = bi[t - 1]; bi[t - 1] = ti;
            }
        }
    }
}

__device__ __forceinline__ void cand_merge(int slot, float (&bd)[10], int (&bi)[10], int lane) {
    for (int r = 0; r < KNN; ++r) {
        ull key = ((ull)fkey(bd[0]) << 32) | (unsigned)bi[0];
        ull mykey = key;
#pragma unroll
        for (int off = 16; off; off >>= 1) {
            ull o = __shfl_xor_sync(0xffffffffu, key, off);
            key = (o < key) ? o : key;
        }
        if (lane == 0) g_cand[slot * KNN + r] = key;
        if (mykey == key) {
#pragma unroll
            for (int t = 0; t < 9; ++t) { bd[t] = bd[t + 1]; bi[t] = bi[t + 1]; }
            bd[9] = 3.4e38f; bi[9] = 0x7fffffff;
        }
    }
}

extern __shared__ ull knn_smem[];
__global__ __launch_bounds__(256) void knn_kernel() {
    ull*  xt  = knn_smem;                       // [64][130] padded
    ull*  qs  = knn_smem + 64 * 130;            // [32][64]
    float* sqs = (float*)(knn_smem + 64 * 130 + 32 * 64);  // [128]
    const int w = threadIdx.x >> 5, lane = threadIdx.x & 31;
    const int tid = threadIdx.x;
    const int i0 = blockIdx.x * 32;
    const int sp = blockIdx.y;
    const ull* xu = (const ull*)g_x;   // row stride 64 pairs

    for (int u = tid; u < 32 * 64; u += 256)
        qs[u] = xu[(i0 + (u >> 6)) * 64 + (u & 63)];

    float bd[4][10]; int bi[4][10];
#pragma unroll
    for (int qi = 0; qi < 4; ++qi)
#pragma unroll
        for (int t = 0; t < 10; ++t) { bd[qi][t] = 3.4e38f; bi[qi][t] = 0x7fffffff; }

    const int j0 = sp * (N_NODES / JSPLIT);
    const int NT = (N_NODES / JSPLIT) / 128;    // 16 tiles

    ull pr[32];
    float prsq = 0.f;

    // preload tile 0 into regs, then to smem
#pragma unroll
    for (int r = 0; r < 32; ++r) {
        int u = tid + 256 * r;
        pr[r] = xu[(j0 + (u >> 6)) * 64 + (u & 63)];
    }
    if (tid < 128) prsq = g_sq[j0 + tid];
#pragma unroll
    for (int r = 0; r < 32; ++r) {
        int u = tid + 256 * r;
        xt[(u & 63) * 130 + (u >> 6)] = pr[r];
    }
    if (tid < 128) sqs[tid] = prsq;
    __syncthreads();

    for (int ti = 0; ti < NT; ++ti) {
        const int jt = j0 + ti * 128;
        // issue next tile's loads into registers (overlaps with compute below)
        if (ti + 1 < NT) {
            const int jn = jt + 128;
#pragma unroll
            for (int r = 0; r < 32; ++r) {
                int u = tid + 256 * r;
                pr[r] = xu[(jn + (u >> 6)) * 64 + (u & 63)];
            }
            if (tid < 128) prsq = g_sq[jn + tid];
        }

        // compute current tile
        ull a[4][4];
#pragma unroll
        for (int qi = 0; qi < 4; ++qi)
#pragma unroll
            for (int c = 0; c < 4; ++c) a[qi][c] = 0ull;

#pragma unroll 4
        for (int dp = 0; dp < 64; ++dp) {
            ull q0 = qs[(w * 4 + 0) * 64 + dp];
            ull q1 = qs[(w * 4 + 1) * 64 + dp];
            ull q2 = qs[(w * 4 + 2) * 64 + dp];
            ull q3 = qs[(w * 4 + 3) * 64 + dp];
            const ull* xr = &xt[dp * 130 + lane];
#pragma unroll
            for (int c = 0; c < 4; ++c) {
                ull xv = xr[c * 32];
                a[0][c] = fma2(q0, xv, a[0][c]);
                a[1][c] = fma2(q1, xv, a[1][c]);
                a[2][c] = fma2(q2, xv, a[2][c]);
                a[3][c] = fma2(q3, xv, a[3][c]);
            }
        }
#pragma unroll
        for (int c = 0; c < 4; ++c) {
            int j = jt + lane + c * 32;
            float sq = sqs[lane + c * 32];
#pragma unroll
            for (int qi = 0; qi < 4; ++qi) {
                float2 t = unpack2(a[qi][c]);
                insert10(fmaf(-2.f, t.x + t.y, sq), j, bd[qi], bi[qi]);
            }
        }

        // swap: store prefetched tile into smem
        if (ti + 1 < NT) {
            __syncthreads();
#pragma unroll
            for (int r = 0; r < 32; ++r) {
                int u = tid + 256 * r;
                xt[(u & 63) * 130 + (u >> 6)] = pr[r];
            }
            if (tid < 128) sqs[tid] = prsq;
            __syncthreads();
        }
    }

#pragma unroll
    for (int qi = 0; qi < 4; ++qi)
        cand_merge(sp * N_NODES + i0 + w * 4 + qi, bd[qi], bi[qi], lane);
}

__global__ void knn_final() {                     // warp per query, merge JSPLIT lists
    int q = blockIdx.x * 8 + (threadIdx.x >> 5);
    int lane = threadIdx.x & 31;
    ull key = (lane < JSPLIT * KNN)
        ? g_cand[((lane / KNN) * N_NODES + q) * KNN + (lane % KNN)]
        : ~0ull;
    for (int r = 0; r < KNN; ++r) {
        ull t = key;
#pragma unroll
        for (int off = 16; off; off >>= 1) {
            ull o = __shfl_xor_sync(0xffffffffu, t, off);
            t = (o < t) ? o : t;
        }
        if (key == t) key = ~0ull;                // keys unique across splits
        if (lane == 0) g_nn[q * KNN + r] = (int)(unsigned)(t & 0xffffffffu);
    }
}

// ---------------- batched GEMM: C_z[M,128] = a_z*(A_z B_z^T + bias_z) -------
__global__ __launch_bounds__(256) void gemm_nt(const float* __restrict__ A0,
                                               const float* __restrict__ A12,
                                               const float* __restrict__ B,
                                               const float* __restrict__ bias,
                                               float* __restrict__ C0,
                                               float* __restrict__ C1,
                                               float* __restrict__ C2,
                                               int M0, float alpha0) {
    const int z = blockIdx.z;
    const int m0 = blockIdx.y * 64, n0 = blockIdx.x * 64;
    if (z == 0 && m0 >= M0) return;
    const float* A = (z == 0) ? A0 : A12;
    float* C = (z == 0) ? C0 : ((z == 1) ? C1 : C2);
    const float* Bz = B + z * 128 * 128;
    const float* bp = bias ? bias + z * 128 : (const float*)0;
    const float alpha = (z == 0) ? alpha0 : 1.f;

    __shared__ float As[64][33], Bs[64][33];
    const int tx = threadIdx.x & 15, ty = threadIdx.x >> 4;
    float acc[4][4] = {};
    const int lrow = threadIdx.x >> 2, lc0 = (threadIdx.x & 3) * 8;
    for (int kc = 0; kc < 128; kc += 32) {
        __syncthreads();
        float4 a0 = *(const float4*)&A[(m0 + lrow) * 128 + kc + lc0];
        float4 a1 = *(const float4*)&A[(m0 + lrow) * 128 + kc + lc0 + 4];
        float4 b0 = *(const float4*)&Bz[(n0 + lrow) * 128 + kc + lc0];
        float4 b1 = *(const float4*)&Bz[(n0 + lrow) * 128 + kc + lc0 + 4];
        As[lrow][lc0 + 0] = a0.x; As[lrow][lc0 + 1] = a0.y; As[lrow][lc0 + 2] = a0.z; As[lrow][lc0 + 3] = a0.w;
        As[lrow][lc0 + 4] = a1.x; As[lrow][lc0 + 5] = a1.y; As[lrow][lc0 + 6] = a1.z; As[lrow][lc0 + 7] = a1.w;
        Bs[lrow][lc0 + 0] = b0.x; Bs[lrow][lc0 + 1] = b0.y; Bs[lrow][lc0 + 2] = b0.z; Bs[lrow][lc0 + 3] = b0.w;
        Bs[lrow][lc0 + 4] = b1.x; Bs[lrow][lc0 + 5] = b1.y; Bs[lrow][lc0 + 6] = b1.z; Bs[lrow][lc0 + 7] = b1.w;
        __syncthreads();
#pragma unroll
        for (int k = 0; k < 32; ++k) {
            float a[4], b[4];
#pragma unroll
            for (int ii = 0; ii < 4; ++ii) a[ii] = As[ty * 4 + ii][k];
#pragma unroll
            for (int jj = 0; jj < 4; ++jj) b[jj] = Bs[tx * 4 + jj][k];
#pragma unroll
            for (int ii = 0; ii < 4; ++ii)
#pragma unroll
                for (int jj = 0; jj < 4; ++jj) acc[ii][jj] = fmaf(a[ii], b[jj], acc[ii][jj]);
        }
    }
#pragma unroll
    for (int ii = 0; ii < 4; ++ii)
#pragma unroll
        for (int jj = 0; jj < 4; ++jj) {
            int cc = n0 + tx * 4 + jj;
            float bv = bp ? bp[cc] : 0.f;
            C[(m0 + ty * 4 + ii) * HID + cc] = alpha * (acc[ii][jj] + bv);
        }
}

// ---------------- flash attention v5: NO online max (scores bounded) -------
__global__ __launch_bounds__(128, 3) void flash_partial(const float* __restrict__ Q,
                                                        const float* __restrict__ Kx,
                                                        const float* __restrict__ Vx,
                                                        int Lq, int Lk, int nsplit) {
    __shared__ ull Ks[32][16], Vs[32][16];
    const int h = blockIdx.y, s = blockIdx.z;
    const int tid = threadIdx.x;
    const int q0 = blockIdx.x * 256 + tid;         // q1 = q0 + 128
    const ull* Qu = (const ull*)Q;
    const ulonglong2* Ku2 = (const ulonglong2*)Kx;
    const ulonglong2* Vu2 = (const ulonglong2*)Vx;

    ull qr0[16], qr1[16];
#pragma unroll
    for (int dp = 0; dp < 16; ++dp) {
        qr0[dp] = Qu[q0 * 64 + h * 16 + dp];
        qr1[dp] = Qu[(q0 + 128) * 64 + h * 16 + dp];
    }

    float l0 = 0.f, l1 = 0.f;
    ull o0[16], o1[16];
#pragma unroll
    for (int dp = 0; dp < 16; ++dp) { o0[dp] = 0ull; o1[dp] = 0ull; }

    const int ntile = Lk >> 5;
    const int t0 = (ntile * s) / nsplit;
    const int t1 = (ntile * (s + 1)) / nsplit;

    for (int t = t0; t < t1; ++t) {
        __syncthreads();
        const int kt = t << 5;
#pragma unroll
        for (int r = 0; r < 2; ++r) {
            int u = tid + r * 128;
            int j = u >> 3, dpp = u & 7;
            ((ulonglong2*)Ks[j])[dpp] = Ku2[(kt + j) * 32 + h * 8 + dpp];
            ((ulonglong2*)Vs[j])[dpp] = Vu2[(kt + j) * 32 + h * 8 + dpp];
        }
        __syncthreads();

#pragma unroll 4
        for (int j = 0; j < 32; ++j) {
            const ulonglong2* kr = (const ulonglong2*)Ks[j];
            ull a0e = 0ull, a0o = 0ull, a1e = 0ull, a1o = 0ull;
#pragma unroll
            for (int i = 0; i < 8; ++i) {
                ulonglong2 kv = kr[i];
                a0e = fma2(qr0[2 * i],     kv.x, a0e);
                a0o = fma2(qr0[2 * i + 1], kv.y, a0o);
                a1e = fma2(qr1[2 * i],     kv.x, a1e);
                a1o = fma2(qr1[2 * i + 1], kv.y, a1o);
            }
            float2 u0 = unpack2(a0e), v0 = unpack2(a0o);
            float2 u1 = unpack2(a1e), v1 = unpack2(a1o);
            float p0 = __expf((u0.x + u0.y) + (v0.x + v0.y));
            float p1 = __expf((u1.x + u1.y) + (v1.x + v1.y));
            l0 += p0; l1 += p1;
            ull p02 = pack2(p0, p0), p12 = pack2(p1, p1);
            const ulonglong2* vr = (const ulonglong2*)Vs[j];
#pragma unroll
            for (int i = 0; i < 8; ++i) {
                ulonglong2 vv = vr[i];
                o0[2 * i]     = fma2(p02, vv.x, o0[2 * i]);
                o0[2 * i + 1] = fma2(p02, vv.y, o0[2 * i + 1]);
                o1[2 * i]     = fma2(p12, vv.x, o1[2 * i]);
                o1[2 * i + 1] = fma2(p12, vv.y, o1[2 * i + 1]);
            }
        }
    }

    ull* po = (ull*)g_po;
    const int pid0 = (s * NH + h) * Lq + q0;
    const int pid1 = pid0 + 128;
    g_pl[pid0] = l0;
    g_pl[pid1] = l1;
#pragma unroll
    for (int dp = 0; dp < 16; ++dp) {
        po[pid0 * 16 + dp] = o0[dp];
        po[pid1 * 16 + dp] = o1[dp];
    }
}

__global__ void flash_combine(float* __restrict__ ao, int Lq, int nsplit) {  // warp per (q,h)
    int gw = blockIdx.x * 8 + (threadIdx.x >> 5);
    int lane = threadIdx.x & 31;
    int q = gw >> 2, h = gw & 3;
    float l = 0.f, ov = 0.f;
    for (int s = 0; s < nsplit; ++s) {
        int pid = (s * NH + h) * Lq + q;
        l  += g_pl[pid];
        ov += g_po[pid * 32 + lane];
    }
    ao[q * HID + h * 32 + lane] = ov / l;
}

// ---------------- neighbor gather-sum (float4) -------------------------------
__global__ void gather_sum() {
    int t = blockIdx.x * 256 + threadIdx.x;   // N*32 threads
    int i = t >> 5, d4 = (t & 31) * 4;
    float4 acc = *(const float4*)&g_x[i * HID + d4];
#pragma unroll
    for (int k = 0; k < KNN; ++k) {
        float4 v = *(const float4*)&g_hf[g_nn[i * KNN + k] * HID + d4];
        acc.x += v.x; acc.y += v.y; acc.z += v.z; acc.w += v.w;
    }
    *(float4*)&g_x2[i * HID + d4] = acc;
}

// ---------------- hypergraph conv -------------------------------------------
__global__ void zero_buffers() {
    int t = blockIdx.x * 256 + threadIdx.x;
    g_ef[t] = 0.f; g_o1[t] = 0.f;
    if (t < N_NODES) { g_dcnt[t] = 0; g_bcnt[t] = 0; }
}

__global__ void he_count(const int* __restrict__ ei) {
    int e = blockIdx.x * 256 + threadIdx.x;
    if (e < NE) {
        atomicAdd(&g_dcnt[ei[e]], 1);
        atomicAdd(&g_bcnt[ei[NE + e]], 1);
    }
}

__global__ void scatter1(const int* __restrict__ ei) {   // node -> hyperedge (v4 red)
    int t = blockIdx.x * 256 + threadIdx.x;   // NE*32 threads
    int e = t >> 5, d4 = (t & 31) * 4;
    int nd = ei[e], hh = ei[NE + e];
    float4 v = *(const float4*)&g_xw[nd * HID + d4];
    red4(&g_ef[hh * HID + d4], v);
}

__global__ void scatter2(const int* __restrict__ ei) {   // hyperedge -> node (B^-1 fused)
    int t = blockIdx.x * 256 + threadIdx.x;   // NE*32 threads
    int e = t >> 5, d4 = (t & 31) * 4;
    int nd = ei[e], hh = ei[NE + e];
    float binv = 1.f / (float)g_bcnt[hh];
    float4 v = *(const float4*)&g_ef[hh * HID + d4];
    v.x *= binv; v.y *= binv; v.z *= binv; v.w *= binv;
    red4(&g_o1[nd * HID + d4], v);
}

__global__ void conv_finalize(const float* __restrict__ convb) {
    int t = blockIdx.x * 256 + threadIdx.x;
    int i = t >> 7, d = t & 127;
    int dc = g_dcnt[i];
    float dinv = dc > 0 ? 1.f / (float)dc : 0.f;
    g_y[t] = g_o1[t] * dinv + convb[d];
}

// ---------------- batchnorm + elu -------------------------------------------
__global__ void bn_stats() {                              // block per column
    __shared__ float ss[256], ss2[256];
    int c = blockIdx.x;
    float s = 0.f, s2 = 0.f;
    for (int i = threadIdx.x; i < N_NODES; i += 256) {
        float v = g_y[i * HID + c];
        s += v; s2 = fmaf(v, v, s2);
    }
    ss[threadIdx.x] = s; ss2[threadIdx.x] = s2;
    __syncthreads();
    for (int st = 128; st > 0; st >>= 1) {
        if (threadIdx.x < st) { ss[threadIdx.x] += ss[threadIdx.x + st]; ss2[threadIdx.x] += ss2[threadIdx.x + st]; }
        __syncthreads();
    }
    if (threadIdx.x == 0) {
        float mean = ss[0] / (float)N_NODES;
        g_mean[c] = mean;
        g_var[c] = ss2[0] / (float)N_NODES - mean * mean;
    }
}

__global__ void bn_apply_elu(const float* __restrict__ gamma, const float* __restrict__ beta) {
    int t = blockIdx.x * 256 + threadIdx.x;
    int d = t & 127;
    float v = (g_y[t] - g_mean[d]) * rsqrtf(g_var[d] + 1e-5f) * gamma[d] + beta[d];
    g_x3[t] = v > 0.f ? v : expm1f(v);
}

// ---------------- host orchestration ----------------------------------------
static float* dsym(const void* sym) {
    void* p = 0;
    cudaGetSymbolAddress(&p, sym);
    return (float*)p;
}

extern "C" void kernel_launch(void* const* d_in, const int* in_sizes, int n_in,
                              void* d_out, int out_size) {
    const float* embs1   = (const float*)d_in[0];
    const float* embs2   = (const float*)d_in[1];
    const float* m_embs  = (const float*)d_in[2];
    const int*   eidx    = (const int*)  d_in[3];
    const float* he_init = (const float*)d_in[4];
    const float* a_in_w  = (const float*)d_in[5];
    const float* a_in_b  = (const float*)d_in[6];
    const float* a_out_w = (const float*)d_in[7];
    const float* a_out_b = (const float*)d_in[8];
    const float* conv_w  = (const float*)d_in[9];
    const float* conv_b  = (const float*)d_in[10];
    const float* bn_g    = (const float*)d_in[11];
    const float* bn_b    = (const float*)d_in[12];
    const float* m_in_w  = (const float*)d_in[13];
    const float* m_in_b  = (const float*)d_in[14];
    const float* m_out_w = (const float*)d_in[15];
    const float* m_out_b = (const float*)d_in[16];
    float* out = (float*)d_out;

    float* p_x  = dsym(g_x);
    float* p_q  = dsym(g_q);
    float* p_k  = dsym(g_k);
    float* p_v  = dsym(g_v);
    float* p_ao = dsym(g_ao);
    float* p_hf = dsym(g_hf);
    float* p_x2 = dsym(g_x2);
    float* p_xw = dsym(g_xw);
    float* p_x3 = dsym(g_x3);

    cudaFuncSetAttribute(knn_kernel, cudaFuncAttributeMaxDynamicSharedMemorySize, KNN_SMEM);

    const float rs = 0.17677669529663687f;  // 1/sqrt(DH)
    const int EW = N_NODES * HID / 256;

    // 1-2: concat, row_sq (prerequisites of both branches)
    concat_k<<<N_NODES * HID / 1024, 256>>>(embs1, embs2);
    row_sq<<<N_NODES / 8, 256>>>();

    // fork: kNN runs on side stream, overlapped with the MHA1 chain
    cudaEventRecord(g_e1, 0);
    cudaStreamWaitEvent(g_s2, g_e1, 0);
    knn_kernel<<<dim3(N_NODES / 32, JSPLIT), 256, KNN_SMEM, g_s2>>>();
    knn_final<<<N_NODES / 8, 256, 0, g_s2>>>();
    cudaEventRecord(g_e2, g_s2);

    // main stream: MHA1 QKV + flash + conv prep + combine + out-proj
    gemm_nt<<<dim3(2, 64, 3), 256>>>(he_init, p_x, a_in_w, a_in_b,
                                     p_q, p_k, p_v, N_NODES, rs);
    flash_partial<<<dim3(N_NODES / 256, NH, 7), 128>>>(p_q, p_k, p_v, N_NODES, N_NODES, 7);
    zero_buffers<<<EW, 256>>>();
    he_count<<<NE / 256, 256>>>(eidx);
    flash_combine<<<N_NODES * NH / 8, 256>>>(p_ao, N_NODES, 7);
    gemm_nt<<<dim3(2, 64, 1), 256>>>(p_ao, p_ao, a_out_w, a_out_b,
                                     p_hf, p_hf, p_hf, N_NODES, 1.f);

    // join: gather_sum needs g_nn from the kNN branch
    cudaStreamWaitEvent(0, g_e2, 0);
    gather_sum<<<N_NODES * 32 / 256, 256>>>();

    // hypergraph conv
    gemm_nt<<<dim3(2, 64, 1), 256>>>(p_x2, p_x2, conv_w, (const float*)0,
                                     p_xw, p_xw, p_xw, N_NODES, 1.f);
    scatter1<<<NE * 32 / 256, 256>>>(eidx);
    scatter2<<<NE * 32 / 256, 256>>>(eidx);
    conv_finalize<<<EW, 256>>>(conv_b);

    // batchnorm + elu
    bn_stats<<<HID, 256>>>();
    bn_apply_elu<<<EW, 256>>>(bn_g, bn_b);

    // MHA2
    gemm_nt<<<dim3(2, 64, 3), 256>>>(m_embs, p_x3, m_in_w, m_in_b,
                                     p_q, p_k, p_v, MQ, rs);
    flash_partial<<<dim3(MQ / 256, NH, 14), 128>>>(p_q, p_k, p_v, MQ, N_NODES, 14);
    flash_combine<<<MQ * NH / 8, 256>>>(p_ao, MQ, 14);
    gemm_nt<<<dim3(2, 32, 1), 256>>>(p_ao, p_ao, m_out_w, m_out_b,
                                     out, out, out, MQ, 1.f);

    (void)in_sizes; (void)n_in; (void)out_size;
}